// round 4
// baseline (speedup 1.0000x reference)
#include <cuda_runtime.h>
#include <cuda_bf16.h>

// Problem shape (fixed for GAT_40870908789103)
#define Nn   50000
#define Ee   800000
#define Fin  128
#define Hh   8
#define Oo   8
#define HO   64          // H*O
#define NEG_SLOPE 0.2f

// Scratch (no allocation allowed -> __device__ globals)
__device__ float g_Wh[(size_t)Nn * HO];     // projected features [N][64]
__device__ float g_ssrc[(size_t)Nn * Hh];   // a1 . Wh[n,h,:]
__device__ float g_sdst[(size_t)Nn * Hh];   // a2 . Wh[n,h,:]
__device__ float g_denom[(size_t)Nn * Hh];  // softmax denominators

// ---------------------------------------------------------------------------
// K1: Wh = h @ W, register-blocked 4x8 per thread.
// Block = 256 threads, tile = 128 rows x 64 cols. Thread (rg,cg) computes
// rows rg*4..rg*4+3 for cols cg*8..cg*8+7 (cols of one head = cg).
// Per f-step: 2 LDS.128 (W, 32B) + 4 scalar LDS (h) feed 32 FMAs.
// Occupancy target: 3 blocks/SM (24 warps) via launch_bounds regs cap.
// Also emits s_src, s_dst (in-register dot with a1/a2) and zeroes g_denom.
// ---------------------------------------------------------------------------
#define FCH 32                      // f-chunk
#define HS_STRIDE 33                // 32 + 1 pad: bank = (row+f) % 32

__global__ __launch_bounds__(256, 3) void k_proj(const float* __restrict__ h,
                                                 const float* __restrict__ W,
                                                 const float* __restrict__ a1,
                                                 const float* __restrict__ a2) {
    __shared__ float Wt[FCH * HO];          // [f_local][64], 8KB
    __shared__ float hs[128 * HS_STRIDE];   // [row][f_local] padded, 16.9KB

    const int tid  = threadIdx.x;
    const int rg   = tid >> 3;              // 0..31 (4 rows each)
    const int cg   = tid & 7;               // 0..7  (head index, 8 cols)
    const int row0 = blockIdx.x * 128;

    float4 acc0[4], acc1[4];
    #pragma unroll
    for (int j = 0; j < 4; j++) {
        acc0[j] = make_float4(0.f, 0.f, 0.f, 0.f);
        acc1[j] = make_float4(0.f, 0.f, 0.f, 0.f);
    }

    for (int fc = 0; fc < Fin; fc += FCH) {
        // Load + transpose W chunk: W[h][fc+fl][o] -> Wt[fl*64 + h*8 + o]
        for (int i = tid; i < FCH * HO; i += 256) {
            int fl  = i >> 6;
            int col = i & 63;
            int hh  = col >> 3;
            int o   = col & 7;
            Wt[i] = W[(size_t)hh * (Fin * Oo) + (fc + fl) * Oo + o];
        }
        // Load h chunk: 128 rows x 32 f as float4 (coalesced), store padded.
        for (int i = tid; i < 128 * (FCH / 4); i += 256) {
            int row  = i >> 3;
            int f4   = i & 7;
            int grow = row0 + row;
            if (grow >= Nn) grow = Nn - 1;          // clamp (harmless dup)
            float4 v = *(const float4*)&h[(size_t)grow * Fin + fc + f4 * 4];
            float* dstp = &hs[row * HS_STRIDE + f4 * 4];
            dstp[0] = v.x; dstp[1] = v.y; dstp[2] = v.z; dstp[3] = v.w;
        }
        __syncthreads();

        #pragma unroll 4
        for (int f = 0; f < FCH; f++) {
            float4 w0 = *(const float4*)&Wt[f * 64 + cg * 8];
            float4 w1 = *(const float4*)&Wt[f * 64 + cg * 8 + 4];
            #pragma unroll
            for (int j = 0; j < 4; j++) {
                float hv = hs[(rg * 4 + j) * HS_STRIDE + f];
                acc0[j].x += hv * w0.x; acc0[j].y += hv * w0.y;
                acc0[j].z += hv * w0.z; acc0[j].w += hv * w0.w;
                acc1[j].x += hv * w1.x; acc1[j].y += hv * w1.y;
                acc1[j].z += hv * w1.z; acc1[j].w += hv * w1.w;
            }
        }
        __syncthreads();
    }

    // Epilogue: store Wh + per-head half-scores (thread owns full head cg).
    float4 a1lo = *(const float4*)&a1[cg * 8];
    float4 a1hi = *(const float4*)&a1[cg * 8 + 4];
    float4 a2lo = *(const float4*)&a2[cg * 8];
    float4 a2hi = *(const float4*)&a2[cg * 8 + 4];

    #pragma unroll
    for (int j = 0; j < 4; j++) {
        int row = row0 + rg * 4 + j;
        if (row < Nn) {
            *(float4*)&g_Wh[(size_t)row * HO + cg * 8]     = acc0[j];
            *(float4*)&g_Wh[(size_t)row * HO + cg * 8 + 4] = acc1[j];
            float s1 = acc0[j].x * a1lo.x + acc0[j].y * a1lo.y +
                       acc0[j].z * a1lo.z + acc0[j].w * a1lo.w +
                       acc1[j].x * a1hi.x + acc1[j].y * a1hi.y +
                       acc1[j].z * a1hi.z + acc1[j].w * a1hi.w;
            float s2 = acc0[j].x * a2lo.x + acc0[j].y * a2lo.y +
                       acc0[j].z * a2lo.z + acc0[j].w * a2lo.w +
                       acc1[j].x * a2hi.x + acc1[j].y * a2hi.y +
                       acc1[j].z * a2hi.z + acc1[j].w * a2hi.w;
            g_ssrc[row * Hh + cg]  = s1;
            g_sdst[row * Hh + cg]  = s2;
            g_denom[row * Hh + cg] = 0.0f;
        }
    }
}

// ---------------------------------------------------------------------------
// K2: fused edge pass. 16 threads/edge (slice t = 0..15, head = t>>1).
// Recomputes p = exp(leaky_relu(s_src[src] + s_dst[dst])) from the tiny
// L2-resident s tables; accumulates BOTH the softmax denominator and the
// UNNORMALIZED message sum (division deferred to k_norm). Max-subtraction
// skipped: |logit| <~ 30, exp stays far below fp32 overflow, and the
// normalized result is analytically identical.
// ---------------------------------------------------------------------------
__global__ __launch_bounds__(256) void k_scatter(const int* __restrict__ src,
                                                 const int* __restrict__ dst,
                                                 float* __restrict__ out) {
    int gid = blockIdx.x * 256 + threadIdx.x;
    int e = gid >> 4;
    if (e >= Ee) return;
    int t  = gid & 15;          // slice 0..15 (4 floats each)
    int hh = t >> 1;            // head of this slice
    int s = __ldg(&src[e]);
    int d = __ldg(&dst[e]);

    float ev = g_ssrc[s * Hh + hh] + g_sdst[d * Hh + hh];
    ev = ev > 0.0f ? ev : NEG_SLOPE * ev;
    float pv = __expf(ev);

    float4 w = *(const float4*)&g_Wh[(size_t)s * HO + t * 4];

    // one lane per (edge, head) accumulates the denominator
    if ((t & 1) == 0) {
        asm volatile("red.global.add.f32 [%0], %1;"
                     :: "l"(&g_denom[d * Hh + hh]), "f"(pv) : "memory");
    }

    float4 v;
    v.x = w.x * pv; v.y = w.y * pv; v.z = w.z * pv; v.w = w.w * pv;

    float* addr = out + (size_t)d * HO + t * 4;   // 16B aligned
    asm volatile("red.global.add.v4.f32 [%0], {%1,%2,%3,%4};"
                 :: "l"(addr), "f"(v.x), "f"(v.y), "f"(v.z), "f"(v.w)
                 : "memory");
}

// ---------------------------------------------------------------------------
// K3: deferred softmax normalization: out[n,h,:] /= max(denom[n,h], 1e-16).
// ---------------------------------------------------------------------------
__global__ __launch_bounds__(256) void k_norm(float* __restrict__ out) {
    int i = blockIdx.x * 256 + threadIdx.x;     // over N*16 float4 slices
    if (i >= Nn * 16) return;
    int n  = i >> 4;
    int t  = i & 15;
    int hh = t >> 1;
    float dnm = g_denom[n * Hh + hh];
    float inv = 1.0f / fmaxf(dnm, 1e-16f);
    float4* p = (float4*)(out + (size_t)n * HO + t * 4);
    float4 v = *p;
    v.x *= inv; v.y *= inv; v.z *= inv; v.w *= inv;
    *p = v;
}

// ---------------------------------------------------------------------------
extern "C" void kernel_launch(void* const* d_in, const int* in_sizes, int n_in,
                              void* d_out, int out_size) {
    const float* h  = (const float*)d_in[0];
    const float* W  = (const float*)d_in[1];
    const float* a1 = (const float*)d_in[2];
    const float* a2 = (const float*)d_in[3];
    const int*  src = (const int*)d_in[4];
    const int*  dst = (const int*)d_in[5];
    float* out = (float*)d_out;

    cudaMemsetAsync(out, 0, (size_t)Nn * HO * sizeof(float));
    k_proj<<<(Nn + 127) / 128, 256>>>(h, W, a1, a2);
    k_scatter<<<(Ee * 16) / 256, 256>>>(src, dst, out);
    k_norm<<<(Nn * 16 + 255) / 256, 256>>>(out);
}